// round 2
// baseline (speedup 1.0000x reference)
#include <cuda_runtime.h>
#include <math.h>

// Problem constants (fixed by the dataset)
#define C_    512
#define N_    16384
#define B_    4
#define NMAT  8          // 4 content covs + 4 style covs
#define EPS_  1e-5f
#define NS_ITERS 10
#define KTILE 16

// ---------------- device scratch (no allocations allowed) ----------------
__device__ float g_mean[2][B_][C_];          // [0]=content means, [1]=style means
__device__ float g_cov[NMAT][C_ * C_];       // covariances
__device__ float g_s[NMAT];                  // spectral scaling s = ||cov||_F / 2.5
__device__ float g_sinv[NMAT];
__device__ float g_Y[NMAT][C_ * C_];         // Newton-Schulz Y (-> A^{1/2}/sqrt(s) dir)
__device__ float g_Z[NMAT][C_ * C_];         // Newton-Schulz Z (-> A^{-1/2}*sqrt(s) dir)
__device__ float g_Y2[NMAT][C_ * C_];        // ping-pong buffers
__device__ float g_Z2[NMAT][C_ * C_];
__device__ float g_G[NMAT][C_ * C_];         // G = (3I - Z*Y)/2
__device__ float g_M[B_][C_ * C_];           // fused transform per batch

// ---------------- per-channel means ----------------
__global__ __launch_bounds__(256) void means_kernel(
    const float* __restrict__ content, const float* __restrict__ style)
{
    int idx = blockIdx.x;                 // 0..4095 = src*2048 + b*512 + c
    int src = idx >> 11;
    int b   = (idx >> 9) & 3;
    int c   = idx & 511;
    const float* X = (src ? style : content) + (size_t)(b * C_ + c) * N_;
    const float4* X4 = (const float4*)X;
    float sum = 0.f;
    for (int i = threadIdx.x; i < N_ / 4; i += 256) {
        float4 v = X4[i];
        sum += (v.x + v.y) + (v.z + v.w);
    }
    __shared__ float red[256];
    red[threadIdx.x] = sum;
    __syncthreads();
    for (int s = 128; s; s >>= 1) {
        if (threadIdx.x < s) red[threadIdx.x] += red[threadIdx.x + s];
        __syncthreads();
    }
    if (threadIdx.x == 0) g_mean[src][b][c] = red[0] * (1.0f / N_);
}

// ---------------- covariance: cov = Xc*Xc^T/(N-1) + eps*I ----------------
// 64x64 tile, 256 threads, 4x4 microtile. Both operands are K-major rows of X.
// Exploit symmetry: only blocks with i-tile <= j-tile compute; mirror on store.
__global__ __launch_bounds__(256) void cov_kernel(
    const float* __restrict__ content, const float* __restrict__ style)
{
    if (blockIdx.y > blockIdx.x) return;   // lower-triangle tiles skipped
    int m   = blockIdx.z;
    int src = m >> 2, b = m & 3;
    const float* X    = (src ? style : content) + (size_t)b * C_ * N_;
    const float* mean = g_mean[src][b];

    int i0 = blockIdx.y * 64, j0 = blockIdx.x * 64;
    __shared__ float As[KTILE][68], Bs[KTILE][68];
    int tid = threadIdx.x;
    int lr = tid >> 2, lq = tid & 3;      // loader: 64 rows x 4 k-quads
    int tx = tid & 15, ty = tid >> 4;     // compute: 16x16 threads, 4x4 each

    float am = mean[i0 + lr];
    float bm = mean[j0 + lr];
    const float* Arow = X + (size_t)(i0 + lr) * N_;
    const float* Brow = X + (size_t)(j0 + lr) * N_;

    float acc[4][4] = {};
    for (int k0 = 0; k0 < N_; k0 += KTILE) {
        float4 av = *(const float4*)(Arow + k0 + lq * 4);
        float4 bv = *(const float4*)(Brow + k0 + lq * 4);
        __syncthreads();
        As[lq*4+0][lr] = av.x - am; As[lq*4+1][lr] = av.y - am;
        As[lq*4+2][lr] = av.z - am; As[lq*4+3][lr] = av.w - am;
        Bs[lq*4+0][lr] = bv.x - bm; Bs[lq*4+1][lr] = bv.y - bm;
        Bs[lq*4+2][lr] = bv.z - bm; Bs[lq*4+3][lr] = bv.w - bm;
        __syncthreads();
#pragma unroll
        for (int k = 0; k < KTILE; k++) {
            float4 a  = *(const float4*)&As[k][ty * 4];
            float4 bb = *(const float4*)&Bs[k][tx * 4];
            acc[0][0] += a.x*bb.x; acc[0][1] += a.x*bb.y; acc[0][2] += a.x*bb.z; acc[0][3] += a.x*bb.w;
            acc[1][0] += a.y*bb.x; acc[1][1] += a.y*bb.y; acc[1][2] += a.y*bb.z; acc[1][3] += a.y*bb.w;
            acc[2][0] += a.z*bb.x; acc[2][1] += a.z*bb.y; acc[2][2] += a.z*bb.z; acc[2][3] += a.z*bb.w;
            acc[3][0] += a.w*bb.x; acc[3][1] += a.w*bb.y; acc[3][2] += a.w*bb.z; acc[3][3] += a.w*bb.w;
        }
    }
    const float inv = 1.0f / (float)(N_ - 1);
#pragma unroll
    for (int i = 0; i < 4; i++) {
        int gi = i0 + ty * 4 + i;
#pragma unroll
        for (int j = 0; j < 4; j++) {
            int gj = j0 + tx * 4 + j;
            float v = acc[i][j] * inv;
            if (gi == gj) v += EPS_;
            g_cov[m][gi * C_ + gj] = v;
            g_cov[m][gj * C_ + gi] = v;   // symmetry mirror (diag tiles idempotent)
        }
    }
}

// ---------------- spectral scale: s = ||cov||_F / 2.5 ----------------
__global__ __launch_bounds__(256) void scale_kernel()
{
    int m = blockIdx.x;
    const float* covm = g_cov[m];
    float ss = 0.f;
    for (int i = threadIdx.x; i < C_ * C_; i += 256) {
        float v = covm[i];
        ss += v * v;
    }
    __shared__ float red[256];
    red[threadIdx.x] = ss;
    __syncthreads();
    for (int s = 128; s; s >>= 1) {
        if (threadIdx.x < s) red[threadIdx.x] += red[threadIdx.x + s];
        __syncthreads();
    }
    if (threadIdx.x == 0) {
        float sc = sqrtf(red[0]) * (1.0f / 2.5f);
        g_s[m]    = sc;
        g_sinv[m] = 1.0f / sc;
    }
}

// ---------------- Y0 = cov/s, Z0 = I ----------------
__global__ __launch_bounds__(256) void init_kernel()
{
    int i = blockIdx.x * 256 + threadIdx.x;    // [0, 8*262144)
    int m = i >> 18;                           // C_*C_ = 2^18
    int r = i & (C_ * C_ - 1);
    float sc = g_sinv[m];
    (&g_Y[0][0])[i] = (&g_cov[0][0])[i] * sc;
    (&g_Z[0][0])[i] = ((r >> 9) == (r & 511)) ? 1.0f : 0.0f;
}

// ---------------- shared 512^3 GEMM tile body ----------------
// C_tile(64x64) = A(row-major 512x512) * B(row-major 512x512)
__device__ __forceinline__ void gemm512_body(
    const float* __restrict__ A, const float* __restrict__ B, float acc[4][4])
{
    __shared__ float As[KTILE][68], Bs[KTILE][68];
    int tid = threadIdx.x;
    int lr = tid >> 2, lq = tid & 3;      // A loader (K-major)
    int kr = tid >> 4, cq = tid & 15;     // B loader (N-major)
    int tx = tid & 15, ty = tid >> 4;
    int i0 = blockIdx.y * 64, j0 = blockIdx.x * 64;
    for (int k0 = 0; k0 < C_; k0 += KTILE) {
        float4 av = *(const float4*)(A + (i0 + lr) * C_ + k0 + lq * 4);
        float4 bv = *(const float4*)(B + (k0 + kr) * C_ + j0 + cq * 4);
        __syncthreads();
        As[lq*4+0][lr] = av.x; As[lq*4+1][lr] = av.y;
        As[lq*4+2][lr] = av.z; As[lq*4+3][lr] = av.w;
        *(float4*)&Bs[kr][cq * 4] = bv;
        __syncthreads();
#pragma unroll
        for (int k = 0; k < KTILE; k++) {
            float4 a  = *(const float4*)&As[k][ty * 4];
            float4 bb = *(const float4*)&Bs[k][tx * 4];
            acc[0][0] += a.x*bb.x; acc[0][1] += a.x*bb.y; acc[0][2] += a.x*bb.z; acc[0][3] += a.x*bb.w;
            acc[1][0] += a.y*bb.x; acc[1][1] += a.y*bb.y; acc[1][2] += a.y*bb.z; acc[1][3] += a.y*bb.w;
            acc[2][0] += a.z*bb.x; acc[2][1] += a.z*bb.y; acc[2][2] += a.z*bb.z; acc[2][3] += a.z*bb.w;
            acc[3][0] += a.w*bb.x; acc[3][1] += a.w*bb.y; acc[3][2] += a.w*bb.z; acc[3][3] += a.w*bb.w;
        }
    }
}

// ---------------- Newton-Schulz step kernels ----------------
// G = (3I - Z*Y)/2
__global__ __launch_bounds__(256) void ns_stepG_kernel(int flag)
{
    int m = blockIdx.z;
    const float* Y = flag ? g_Y2[m] : g_Y[m];
    const float* Z = flag ? g_Z2[m] : g_Z[m];
    float acc[4][4] = {};
    gemm512_body(Z, Y, acc);
    int tx = threadIdx.x & 15, ty = threadIdx.x >> 4;
    int i0 = blockIdx.y * 64, j0 = blockIdx.x * 64;
#pragma unroll
    for (int i = 0; i < 4; i++) {
        int gi = i0 + ty * 4 + i;
#pragma unroll
        for (int j = 0; j < 4; j++) {
            int gj = j0 + tx * 4 + j;
            float v = -0.5f * acc[i][j] + ((gi == gj) ? 1.5f : 0.0f);
            g_G[m][gi * C_ + gj] = v;
        }
    }
}

// Ynext = Y*G  (z<8)  and  Znext = G*Z  (z>=8), fused into one launch
__global__ __launch_bounds__(256) void ns_stepYZ_kernel(int flag)
{
    int z = blockIdx.z;
    int m = z & 7;
    float acc[4][4] = {};
    float* dst;
    if (z < 8) {
        const float* Ys = flag ? g_Y2[m] : g_Y[m];
        dst             = flag ? g_Y[m]  : g_Y2[m];
        gemm512_body(Ys, g_G[m], acc);
    } else {
        const float* Zs = flag ? g_Z2[m] : g_Z[m];
        dst             = flag ? g_Z[m]  : g_Z2[m];
        gemm512_body(g_G[m], Zs, acc);
    }
    int tx = threadIdx.x & 15, ty = threadIdx.x >> 4;
    int i0 = blockIdx.y * 64, j0 = blockIdx.x * 64;
#pragma unroll
    for (int i = 0; i < 4; i++) {
        int gi = i0 + ty * 4 + i;
#pragma unroll
        for (int j = 0; j < 4; j++)
            dst[gi * C_ + j0 + tx * 4 + j] = acc[i][j];
    }
}

// ---------------- M[b] = sqrt(s_style/s_content) * Y_style[b] @ Z_content[b] ----------------
__global__ __launch_bounds__(256) void combine_kernel()
{
    int b = blockIdx.z;
    float alpha = sqrtf(g_s[4 + b] / g_s[b]);
    float acc[4][4] = {};
    gemm512_body(g_Y[4 + b], g_Z[b], acc);
    int tx = threadIdx.x & 15, ty = threadIdx.x >> 4;
    int i0 = blockIdx.y * 64, j0 = blockIdx.x * 64;
#pragma unroll
    for (int i = 0; i < 4; i++) {
        int gi = i0 + ty * 4 + i;
#pragma unroll
        for (int j = 0; j < 4; j++)
            g_M[b][gi * C_ + j0 + tx * 4 + j] = alpha * acc[i][j];
    }
}

// ---------------- out[b] = M[b] @ (content[b] - c_mean) + s_mean ----------------
__global__ __launch_bounds__(256) void apply_kernel(
    const float* __restrict__ content, float* __restrict__ out)
{
    int b = blockIdx.z;
    const float* A = g_M[b];
    const float* X = content + (size_t)b * C_ * N_;
    float*       O = out     + (size_t)b * C_ * N_;
    const float* cmean = g_mean[0][b];
    const float* smean = g_mean[1][b];

    __shared__ float As[KTILE][68], Bs[KTILE][68];
    int tid = threadIdx.x;
    int lr = tid >> 2, lq = tid & 3;
    int kr = tid >> 4, cq = tid & 15;
    int tx = tid & 15, ty = tid >> 4;
    int i0 = blockIdx.y * 64;
    size_t j0 = (size_t)blockIdx.x * 64;

    float acc[4][4] = {};
    for (int k0 = 0; k0 < C_; k0 += KTILE) {
        float4 av = *(const float4*)(A + (i0 + lr) * C_ + k0 + lq * 4);
        float mk  = cmean[k0 + kr];
        float4 bv = *(const float4*)(X + (size_t)(k0 + kr) * N_ + j0 + cq * 4);
        bv.x -= mk; bv.y -= mk; bv.z -= mk; bv.w -= mk;
        __syncthreads();
        As[lq*4+0][lr] = av.x; As[lq*4+1][lr] = av.y;
        As[lq*4+2][lr] = av.z; As[lq*4+3][lr] = av.w;
        *(float4*)&Bs[kr][cq * 4] = bv;
        __syncthreads();
#pragma unroll
        for (int k = 0; k < KTILE; k++) {
            float4 a  = *(const float4*)&As[k][ty * 4];
            float4 bb = *(const float4*)&Bs[k][tx * 4];
            acc[0][0] += a.x*bb.x; acc[0][1] += a.x*bb.y; acc[0][2] += a.x*bb.z; acc[0][3] += a.x*bb.w;
            acc[1][0] += a.y*bb.x; acc[1][1] += a.y*bb.y; acc[1][2] += a.y*bb.z; acc[1][3] += a.y*bb.w;
            acc[2][0] += a.z*bb.x; acc[2][1] += a.z*bb.y; acc[2][2] += a.z*bb.z; acc[2][3] += a.z*bb.w;
            acc[3][0] += a.w*bb.x; acc[3][1] += a.w*bb.y; acc[3][2] += a.w*bb.z; acc[3][3] += a.w*bb.w;
        }
    }
#pragma unroll
    for (int i = 0; i < 4; i++) {
        int gi = i0 + ty * 4 + i;
        float sm = smean[gi];
        float4 v = make_float4(acc[i][0] + sm, acc[i][1] + sm, acc[i][2] + sm, acc[i][3] + sm);
        *(float4*)(O + (size_t)gi * N_ + j0 + tx * 4) = v;
    }
}

// ---------------- launch sequence (graph-capturable, deterministic) ----------------
extern "C" void kernel_launch(void* const* d_in, const int* in_sizes, int n_in,
                              void* d_out, int out_size)
{
    const float* content = (const float*)d_in[0];
    const float* style   = (const float*)d_in[1];
    float* out = (float*)d_out;

    means_kernel<<<4096, 256>>>(content, style);
    cov_kernel<<<dim3(8, 8, NMAT), 256>>>(content, style);
    scale_kernel<<<NMAT, 256>>>();
    init_kernel<<<NMAT * C_ * C_ / 256, 256>>>();

    for (int it = 0; it < NS_ITERS; it++) {
        int flag = it & 1;
        ns_stepG_kernel<<<dim3(8, 8, NMAT), 256>>>(flag);
        ns_stepYZ_kernel<<<dim3(8, 8, NMAT * 2), 256>>>(flag);
    }

    combine_kernel<<<dim3(8, 8, B_), 256>>>();
    apply_kernel<<<dim3(N_ / 64, C_ / 64, B_), 256>>>(content, out);
}

// round 3
// speedup vs baseline: 1.0011x; 1.0011x over previous
#include <cuda_runtime.h>
#include <math.h>

// Problem constants (fixed by the dataset)
#define C_    512
#define N_    16384
#define B_    4
#define NMAT  8          // 4 content covs + 4 style covs
#define EPS_  1e-5f
#define NS_ITERS 10
#define KTILE 16

// ---------------- device scratch (no allocations allowed) ----------------
__device__ float g_mean[2][B_][C_];          // [0]=content means, [1]=style means
__device__ float g_cov[NMAT][C_ * C_];       // covariances
__device__ float g_s[NMAT];                  // spectral scaling s = ||cov||_F / 2.5
__device__ float g_sinv[NMAT];
__device__ float g_Y[NMAT][C_ * C_];         // Newton-Schulz Y (-> A^{1/2}/sqrt(s) dir)
__device__ float g_Z[NMAT][C_ * C_];         // Newton-Schulz Z (-> A^{-1/2}*sqrt(s) dir)
__device__ float g_Y2[NMAT][C_ * C_];        // ping-pong buffers
__device__ float g_Z2[NMAT][C_ * C_];
__device__ float g_G[NMAT][C_ * C_];         // G = (3I - Z*Y)/2
__device__ float g_M[B_][C_ * C_];           // fused transform per batch

// ---------------- per-channel means ----------------
__global__ __launch_bounds__(256) void means_kernel(
    const float* __restrict__ content, const float* __restrict__ style)
{
    int idx = blockIdx.x;                 // 0..4095 = src*2048 + b*512 + c
    int src = idx >> 11;
    int b   = (idx >> 9) & 3;
    int c   = idx & 511;
    const float* X = (src ? style : content) + (size_t)(b * C_ + c) * N_;
    const float4* X4 = (const float4*)X;
    float sum = 0.f;
    for (int i = threadIdx.x; i < N_ / 4; i += 256) {
        float4 v = X4[i];
        sum += (v.x + v.y) + (v.z + v.w);
    }
    __shared__ float red[256];
    red[threadIdx.x] = sum;
    __syncthreads();
    for (int s = 128; s; s >>= 1) {
        if (threadIdx.x < s) red[threadIdx.x] += red[threadIdx.x + s];
        __syncthreads();
    }
    if (threadIdx.x == 0) g_mean[src][b][c] = red[0] * (1.0f / N_);
}

// ---------------- covariance: cov = Xc*Xc^T/(N-1) + eps*I ----------------
// 64x64 tile, 256 threads, 4x4 microtile. Both operands are K-major rows of X.
// Exploit symmetry: only blocks with i-tile <= j-tile compute; mirror on store.
__global__ __launch_bounds__(256) void cov_kernel(
    const float* __restrict__ content, const float* __restrict__ style)
{
    if (blockIdx.y > blockIdx.x) return;   // lower-triangle tiles skipped
    int m   = blockIdx.z;
    int src = m >> 2, b = m & 3;
    const float* X    = (src ? style : content) + (size_t)b * C_ * N_;
    const float* mean = g_mean[src][b];

    int i0 = blockIdx.y * 64, j0 = blockIdx.x * 64;
    __shared__ float As[KTILE][68], Bs[KTILE][68];
    int tid = threadIdx.x;
    int lr = tid >> 2, lq = tid & 3;      // loader: 64 rows x 4 k-quads
    int tx = tid & 15, ty = tid >> 4;     // compute: 16x16 threads, 4x4 each

    float am = mean[i0 + lr];
    float bm = mean[j0 + lr];
    const float* Arow = X + (size_t)(i0 + lr) * N_;
    const float* Brow = X + (size_t)(j0 + lr) * N_;

    float acc[4][4] = {};
    for (int k0 = 0; k0 < N_; k0 += KTILE) {
        float4 av = *(const float4*)(Arow + k0 + lq * 4);
        float4 bv = *(const float4*)(Brow + k0 + lq * 4);
        __syncthreads();
        As[lq*4+0][lr] = av.x - am; As[lq*4+1][lr] = av.y - am;
        As[lq*4+2][lr] = av.z - am; As[lq*4+3][lr] = av.w - am;
        Bs[lq*4+0][lr] = bv.x - bm; Bs[lq*4+1][lr] = bv.y - bm;
        Bs[lq*4+2][lr] = bv.z - bm; Bs[lq*4+3][lr] = bv.w - bm;
        __syncthreads();
#pragma unroll
        for (int k = 0; k < KTILE; k++) {
            float4 a  = *(const float4*)&As[k][ty * 4];
            float4 bb = *(const float4*)&Bs[k][tx * 4];
            acc[0][0] += a.x*bb.x; acc[0][1] += a.x*bb.y; acc[0][2] += a.x*bb.z; acc[0][3] += a.x*bb.w;
            acc[1][0] += a.y*bb.x; acc[1][1] += a.y*bb.y; acc[1][2] += a.y*bb.z; acc[1][3] += a.y*bb.w;
            acc[2][0] += a.z*bb.x; acc[2][1] += a.z*bb.y; acc[2][2] += a.z*bb.z; acc[2][3] += a.z*bb.w;
            acc[3][0] += a.w*bb.x; acc[3][1] += a.w*bb.y; acc[3][2] += a.w*bb.z; acc[3][3] += a.w*bb.w;
        }
    }
    const float inv = 1.0f / (float)(N_ - 1);
#pragma unroll
    for (int i = 0; i < 4; i++) {
        int gi = i0 + ty * 4 + i;
#pragma unroll
        for (int j = 0; j < 4; j++) {
            int gj = j0 + tx * 4 + j;
            float v = acc[i][j] * inv;
            if (gi == gj) v += EPS_;
            g_cov[m][gi * C_ + gj] = v;
            g_cov[m][gj * C_ + gi] = v;   // symmetry mirror (diag tiles idempotent)
        }
    }
}

// ---------------- spectral scale: s = ||cov||_F / 2.5 ----------------
__global__ __launch_bounds__(256) void scale_kernel()
{
    int m = blockIdx.x;
    const float* covm = g_cov[m];
    float ss = 0.f;
    for (int i = threadIdx.x; i < C_ * C_; i += 256) {
        float v = covm[i];
        ss += v * v;
    }
    __shared__ float red[256];
    red[threadIdx.x] = ss;
    __syncthreads();
    for (int s = 128; s; s >>= 1) {
        if (threadIdx.x < s) red[threadIdx.x] += red[threadIdx.x + s];
        __syncthreads();
    }
    if (threadIdx.x == 0) {
        float sc = sqrtf(red[0]) * (1.0f / 2.5f);
        g_s[m]    = sc;
        g_sinv[m] = 1.0f / sc;
    }
}

// ---------------- Y0 = cov/s, Z0 = I ----------------
__global__ __launch_bounds__(256) void init_kernel()
{
    int i = blockIdx.x * 256 + threadIdx.x;    // [0, 8*262144)
    int m = i >> 18;                           // C_*C_ = 2^18
    int r = i & (C_ * C_ - 1);
    float sc = g_sinv[m];
    (&g_Y[0][0])[i] = (&g_cov[0][0])[i] * sc;
    (&g_Z[0][0])[i] = ((r >> 9) == (r & 511)) ? 1.0f : 0.0f;
}

// ---------------- shared 512^3 GEMM tile body ----------------
// C_tile(64x64) = A(row-major 512x512) * B(row-major 512x512)
__device__ __forceinline__ void gemm512_body(
    const float* __restrict__ A, const float* __restrict__ B, float acc[4][4])
{
    __shared__ float As[KTILE][68], Bs[KTILE][68];
    int tid = threadIdx.x;
    int lr = tid >> 2, lq = tid & 3;      // A loader (K-major)
    int kr = tid >> 4, cq = tid & 15;     // B loader (N-major)
    int tx = tid & 15, ty = tid >> 4;
    int i0 = blockIdx.y * 64, j0 = blockIdx.x * 64;
    for (int k0 = 0; k0 < C_; k0 += KTILE) {
        float4 av = *(const float4*)(A + (i0 + lr) * C_ + k0 + lq * 4);
        float4 bv = *(const float4*)(B + (k0 + kr) * C_ + j0 + cq * 4);
        __syncthreads();
        As[lq*4+0][lr] = av.x; As[lq*4+1][lr] = av.y;
        As[lq*4+2][lr] = av.z; As[lq*4+3][lr] = av.w;
        *(float4*)&Bs[kr][cq * 4] = bv;
        __syncthreads();
#pragma unroll
        for (int k = 0; k < KTILE; k++) {
            float4 a  = *(const float4*)&As[k][ty * 4];
            float4 bb = *(const float4*)&Bs[k][tx * 4];
            acc[0][0] += a.x*bb.x; acc[0][1] += a.x*bb.y; acc[0][2] += a.x*bb.z; acc[0][3] += a.x*bb.w;
            acc[1][0] += a.y*bb.x; acc[1][1] += a.y*bb.y; acc[1][2] += a.y*bb.z; acc[1][3] += a.y*bb.w;
            acc[2][0] += a.z*bb.x; acc[2][1] += a.z*bb.y; acc[2][2] += a.z*bb.z; acc[2][3] += a.z*bb.w;
            acc[3][0] += a.w*bb.x; acc[3][1] += a.w*bb.y; acc[3][2] += a.w*bb.z; acc[3][3] += a.w*bb.w;
        }
    }
}

// ---------------- Newton-Schulz step kernels ----------------
// G = (3I - Z*Y)/2
__global__ __launch_bounds__(256) void ns_stepG_kernel(int flag)
{
    int m = blockIdx.z;
    const float* Y = flag ? g_Y2[m] : g_Y[m];
    const float* Z = flag ? g_Z2[m] : g_Z[m];
    float acc[4][4] = {};
    gemm512_body(Z, Y, acc);
    int tx = threadIdx.x & 15, ty = threadIdx.x >> 4;
    int i0 = blockIdx.y * 64, j0 = blockIdx.x * 64;
#pragma unroll
    for (int i = 0; i < 4; i++) {
        int gi = i0 + ty * 4 + i;
#pragma unroll
        for (int j = 0; j < 4; j++) {
            int gj = j0 + tx * 4 + j;
            float v = -0.5f * acc[i][j] + ((gi == gj) ? 1.5f : 0.0f);
            g_G[m][gi * C_ + gj] = v;
        }
    }
}

// Ynext = Y*G  (z<8)  and  Znext = G*Z  (z>=8), fused into one launch
__global__ __launch_bounds__(256) void ns_stepYZ_kernel(int flag)
{
    int z = blockIdx.z;
    int m = z & 7;
    float acc[4][4] = {};
    float* dst;
    if (z < 8) {
        const float* Ys = flag ? g_Y2[m] : g_Y[m];
        dst             = flag ? g_Y[m]  : g_Y2[m];
        gemm512_body(Ys, g_G[m], acc);
    } else {
        const float* Zs = flag ? g_Z2[m] : g_Z[m];
        dst             = flag ? g_Z[m]  : g_Z2[m];
        gemm512_body(g_G[m], Zs, acc);
    }
    int tx = threadIdx.x & 15, ty = threadIdx.x >> 4;
    int i0 = blockIdx.y * 64, j0 = blockIdx.x * 64;
#pragma unroll
    for (int i = 0; i < 4; i++) {
        int gi = i0 + ty * 4 + i;
#pragma unroll
        for (int j = 0; j < 4; j++)
            dst[gi * C_ + j0 + tx * 4 + j] = acc[i][j];
    }
}

// ---------------- M[b] = sqrt(s_style/s_content) * Y_style[b] @ Z_content[b] ----------------
__global__ __launch_bounds__(256) void combine_kernel()
{
    int b = blockIdx.z;
    float alpha = sqrtf(g_s[4 + b] / g_s[b]);
    float acc[4][4] = {};
    gemm512_body(g_Y[4 + b], g_Z[b], acc);
    int tx = threadIdx.x & 15, ty = threadIdx.x >> 4;
    int i0 = blockIdx.y * 64, j0 = blockIdx.x * 64;
#pragma unroll
    for (int i = 0; i < 4; i++) {
        int gi = i0 + ty * 4 + i;
#pragma unroll
        for (int j = 0; j < 4; j++)
            g_M[b][gi * C_ + j0 + tx * 4 + j] = alpha * acc[i][j];
    }
}

// ---------------- out[b] = M[b] @ (content[b] - c_mean) + s_mean ----------------
__global__ __launch_bounds__(256) void apply_kernel(
    const float* __restrict__ content, float* __restrict__ out)
{
    int b = blockIdx.z;
    const float* A = g_M[b];
    const float* X = content + (size_t)b * C_ * N_;
    float*       O = out     + (size_t)b * C_ * N_;
    const float* cmean = g_mean[0][b];
    const float* smean = g_mean[1][b];

    __shared__ float As[KTILE][68], Bs[KTILE][68];
    int tid = threadIdx.x;
    int lr = tid >> 2, lq = tid & 3;
    int kr = tid >> 4, cq = tid & 15;
    int tx = tid & 15, ty = tid >> 4;
    int i0 = blockIdx.y * 64;
    size_t j0 = (size_t)blockIdx.x * 64;

    float acc[4][4] = {};
    for (int k0 = 0; k0 < C_; k0 += KTILE) {
        float4 av = *(const float4*)(A + (i0 + lr) * C_ + k0 + lq * 4);
        float mk  = cmean[k0 + kr];
        float4 bv = *(const float4*)(X + (size_t)(k0 + kr) * N_ + j0 + cq * 4);
        bv.x -= mk; bv.y -= mk; bv.z -= mk; bv.w -= mk;
        __syncthreads();
        As[lq*4+0][lr] = av.x; As[lq*4+1][lr] = av.y;
        As[lq*4+2][lr] = av.z; As[lq*4+3][lr] = av.w;
        *(float4*)&Bs[kr][cq * 4] = bv;
        __syncthreads();
#pragma unroll
        for (int k = 0; k < KTILE; k++) {
            float4 a  = *(const float4*)&As[k][ty * 4];
            float4 bb = *(const float4*)&Bs[k][tx * 4];
            acc[0][0] += a.x*bb.x; acc[0][1] += a.x*bb.y; acc[0][2] += a.x*bb.z; acc[0][3] += a.x*bb.w;
            acc[1][0] += a.y*bb.x; acc[1][1] += a.y*bb.y; acc[1][2] += a.y*bb.z; acc[1][3] += a.y*bb.w;
            acc[2][0] += a.z*bb.x; acc[2][1] += a.z*bb.y; acc[2][2] += a.z*bb.z; acc[2][3] += a.z*bb.w;
            acc[3][0] += a.w*bb.x; acc[3][1] += a.w*bb.y; acc[3][2] += a.w*bb.z; acc[3][3] += a.w*bb.w;
        }
    }
#pragma unroll
    for (int i = 0; i < 4; i++) {
        int gi = i0 + ty * 4 + i;
        float sm = smean[gi];
        float4 v = make_float4(acc[i][0] + sm, acc[i][1] + sm, acc[i][2] + sm, acc[i][3] + sm);
        *(float4*)(O + (size_t)gi * N_ + j0 + tx * 4) = v;
    }
}

// ---------------- launch sequence (graph-capturable, deterministic) ----------------
extern "C" void kernel_launch(void* const* d_in, const int* in_sizes, int n_in,
                              void* d_out, int out_size)
{
    const float* content = (const float*)d_in[0];
    const float* style   = (const float*)d_in[1];
    float* out = (float*)d_out;

    means_kernel<<<4096, 256>>>(content, style);
    cov_kernel<<<dim3(8, 8, NMAT), 256>>>(content, style);
    scale_kernel<<<NMAT, 256>>>();
    init_kernel<<<NMAT * C_ * C_ / 256, 256>>>();

    for (int it = 0; it < NS_ITERS; it++) {
        int flag = it & 1;
        ns_stepG_kernel<<<dim3(8, 8, NMAT), 256>>>(flag);
        ns_stepYZ_kernel<<<dim3(8, 8, NMAT * 2), 256>>>(flag);
    }

    combine_kernel<<<dim3(8, 8, B_), 256>>>();
    apply_kernel<<<dim3(N_ / 64, C_ / 64, B_), 256>>>(content, out);
}

// round 7
// speedup vs baseline: 2.4813x; 2.4785x over previous
#include <cuda_runtime.h>
#include <cuda_bf16.h>
#include <math.h>
#include <stdint.h>

#define C_    512
#define N_    16384
#define B_    4
#define NMAT  8
#define EPS_  1e-5f
#define NS_ITERS 10

#define MODE_COV     0
#define MODE_G       1
#define MODE_YZ      2
#define MODE_COMBINE 3
#define MODE_APPLY   4

// SMEM: 4 tensors x 128 rows x 40(pad) bf16 = 10240B each; stage = 40960B; 2 stages
#define TEN_BYTES  10240
#define STAGE_BYTES 40960
#define SMEM_DYN   81920

// ---------------- device scratch (no allocations allowed) ----------------
__device__ float g_mean[2][B_][C_];                  // [0]=content, [1]=style
__device__ float g_cov[NMAT][C_ * C_];
__device__ float g_s[NMAT], g_sinv[NMAT];
__device__ __nv_bfloat16 g_xh[2][B_][C_][N_];        // centered hi  [src][b][c][n]
__device__ __nv_bfloat16 g_xm[2][B_][C_][N_];        // centered mid
__device__ __nv_bfloat16 g_th[B_][N_][C_];           // content^T centered hi
__device__ __nv_bfloat16 g_tm[B_][N_][C_];           // content^T centered mid
__device__ __nv_bfloat16 g_Yh[2][NMAT][C_ * C_], g_Ym[2][NMAT][C_ * C_];
__device__ __nv_bfloat16 g_Zh[2][NMAT][C_ * C_], g_Zm[2][NMAT][C_ * C_];
__device__ __nv_bfloat16 g_Gh[NMAT][C_ * C_], g_Gm[NMAT][C_ * C_];
__device__ __nv_bfloat16 g_Mh[B_][C_ * C_], g_Mm[B_][C_ * C_];

// ---------------- PTX helpers (all sm_80+ features only) ----------------
__device__ __forceinline__ uint32_t smem_u32(const void* p) {
    uint32_t a;
    asm("{ .reg .u64 t; cvta.to.shared.u64 t, %1; cvt.u32.u64 %0, t; }" : "=r"(a) : "l"(p));
    return a;
}
#define CP_ASYNC(dst, src) asm volatile("cp.async.cg.shared.global [%0], [%1], 16;" :: "r"(dst), "l"(src))
#define CP_COMMIT()        asm volatile("cp.async.commit_group;" ::: "memory")
#define CP_WAIT1()         asm volatile("cp.async.wait_group 1;" ::: "memory")
#define CP_WAIT0()         asm volatile("cp.async.wait_group 0;" ::: "memory")

__device__ __forceinline__ void ldsm4(uint32_t* r, uint32_t addr) {
    asm volatile("ldmatrix.sync.aligned.m8n8.x4.shared.b16 {%0,%1,%2,%3}, [%4];"
        : "=r"(r[0]), "=r"(r[1]), "=r"(r[2]), "=r"(r[3]) : "r"(addr));
}
__device__ __forceinline__ void mma16816(float* c, const uint32_t* a, const uint32_t* b) {
    asm volatile("mma.sync.aligned.m16n8k16.row.col.f32.bf16.bf16.f32 "
        "{%0,%1,%2,%3}, {%4,%5,%6,%7}, {%8,%9}, {%0,%1,%2,%3};"
        : "+f"(c[0]), "+f"(c[1]), "+f"(c[2]), "+f"(c[3])
        : "r"(a[0]), "r"(a[1]), "r"(a[2]), "r"(a[3]), "r"(b[0]), "r"(b[1]));
}
__device__ __forceinline__ void split2(float v, __nv_bfloat16& h, __nv_bfloat16& m) {
    h = __float2bfloat16(v);
    m = __float2bfloat16(v - __bfloat162float(h));
}

// ---------------- prep kernels ----------------
__global__ __launch_bounds__(256) void means_kernel(
    const float* __restrict__ content, const float* __restrict__ style)
{
    int idx = blockIdx.x;
    int src = idx >> 11, b = (idx >> 9) & 3, c = idx & 511;
    const float* X = (src ? style : content) + (size_t)(b * C_ + c) * N_;
    const float4* X4 = (const float4*)X;
    float sum = 0.f;
    for (int i = threadIdx.x; i < N_ / 4; i += 256) {
        float4 v = X4[i];
        sum += (v.x + v.y) + (v.z + v.w);
    }
    __shared__ float red[256];
    red[threadIdx.x] = sum;
    __syncthreads();
    for (int s = 128; s; s >>= 1) {
        if (threadIdx.x < s) red[threadIdx.x] += red[threadIdx.x + s];
        __syncthreads();
    }
    if (threadIdx.x == 0) g_mean[src][b][c] = red[0] * (1.0f / N_);
}

__global__ __launch_bounds__(256) void split_kernel(
    const float* __restrict__ content, const float* __restrict__ style)
{
    int idx = blockIdx.x;
    int src = idx >> 11, b = (idx >> 9) & 3, c = idx & 511;
    const float* X = (src ? style : content) + (size_t)(b * C_ + c) * N_;
    float mu = g_mean[src][b][c];
    __nv_bfloat162* H = (__nv_bfloat162*)&g_xh[src][b][c][0];
    __nv_bfloat162* M = (__nv_bfloat162*)&g_xm[src][b][c][0];
    for (int i = threadIdx.x; i < N_ / 4; i += 256) {
        float4 v = ((const float4*)X)[i];
        __nv_bfloat16 h0, m0, h1, m1, h2, m2, h3, m3;
        split2(v.x - mu, h0, m0); split2(v.y - mu, h1, m1);
        split2(v.z - mu, h2, m2); split2(v.w - mu, h3, m3);
        __nv_bfloat162 a, b2;
        a.x = h0; a.y = h1; b2.x = h2; b2.y = h3;
        H[2 * i] = a; H[2 * i + 1] = b2;
        a.x = m0; a.y = m1; b2.x = m2; b2.y = m3;
        M[2 * i] = a; M[2 * i + 1] = b2;
    }
}

__global__ __launch_bounds__(256) void transpose_kernel(const float* __restrict__ content)
{
    __shared__ float t[32][33];
    int b = blockIdx.z;
    int n0 = blockIdx.x * 32, c0 = blockIdx.y * 32;
    int tx = threadIdx.x & 31, ty = threadIdx.x >> 5;   // 32 x 8
    const float* X = content + (size_t)b * C_ * N_;
#pragma unroll
    for (int j = 0; j < 32; j += 8) {
        int c = c0 + ty + j;
        t[ty + j][tx] = X[(size_t)c * N_ + n0 + tx] - g_mean[0][b][c];
    }
    __syncthreads();
#pragma unroll
    for (int j = 0; j < 32; j += 8) {
        int n = n0 + ty + j, c = c0 + tx;
        __nv_bfloat16 h, m;
        split2(t[tx][ty + j], h, m);
        g_th[b][n][c] = h;
        g_tm[b][n][c] = m;
    }
}

__global__ __launch_bounds__(256) void scale_kernel()
{
    int m = blockIdx.x;
    const float* covm = g_cov[m];
    float ss = 0.f;
    for (int i = threadIdx.x; i < C_ * C_; i += 256) {
        float v = covm[i];
        ss += v * v;
    }
    __shared__ float red[256];
    red[threadIdx.x] = ss;
    __syncthreads();
    for (int s = 128; s; s >>= 1) {
        if (threadIdx.x < s) red[threadIdx.x] += red[threadIdx.x + s];
        __syncthreads();
    }
    if (threadIdx.x == 0) {
        float sc = sqrtf(red[0]) * (1.0f / 2.5f);
        g_s[m] = sc;
        g_sinv[m] = 1.0f / sc;
    }
}

__global__ __launch_bounds__(256) void init_ns_kernel()
{
    int i = blockIdx.x * 256 + threadIdx.x;   // 8 * 262144
    int m = i >> 18;
    int r = i & (C_ * C_ - 1);
    float v = g_cov[m][r] * g_sinv[m];
    __nv_bfloat16 h, mm;
    split2(v, h, mm);
    g_Yh[0][m][r] = h;
    g_Ym[0][m][r] = mm;
    bool dg = ((r >> 9) == (r & 511));
    g_Zh[0][m][r] = __float2bfloat16(dg ? 1.0f : 0.0f);
    g_Zm[0][m][r] = __float2bfloat16(0.0f);
}

// ---------------- cp.async stage fill: 4 tensors x 128 rows x 32 bf16 ----------------
__device__ __forceinline__ void fill_stage(uint32_t sbase,
    const __nv_bfloat16* ah, const __nv_bfloat16* am,
    const __nv_bfloat16* bh, const __nv_bfloat16* bm,
    long sA, long sB, int tid)
{
#pragma unroll
    for (int t = tid; t < 512; t += 256) {
        int row = t >> 2, q = (t & 3) * 8;
        uint32_t d = sbase + (uint32_t)(row * 40 + q) * 2;
        long oa = (long)row * sA + q, ob = (long)row * sB + q;
        CP_ASYNC(d,                 ah + oa);
        CP_ASYNC(d + TEN_BYTES,     am + oa);
        CP_ASYNC(d + 2 * TEN_BYTES, bh + ob);
        CP_ASYNC(d + 3 * TEN_BYTES, bm + ob);
    }
}

// ---------------- warp-MMA tile GEMM: D(128x128) = A * B^T, bf16 hi/mid split ----------------
__global__ __launch_bounds__(256) void mma_kernel(int mode, int flag, float* __restrict__ outp)
{
    int bx = blockIdx.x, by = blockIdx.y, bz = blockIdx.z;
    bool sym = (mode <= MODE_YZ);
    if (sym && by > bx) return;               // upper-triangle tiles only; mirror in epilogue
    int i0 = by * 128, j0 = bx * 128;

    const __nv_bfloat16 *Ah, *Am, *Bh, *Bm;
    long sA, sB;
    int K;
    if (mode == MODE_COV) {
        int src = bz >> 2, b = bz & 3;
        Ah = &g_xh[src][b][i0][0]; Am = &g_xm[src][b][i0][0];
        Bh = &g_xh[src][b][j0][0]; Bm = &g_xm[src][b][j0][0];
        sA = sB = N_; K = N_;
    } else if (mode == MODE_G) {              // G = (3I - Z*Y)/2 ; D = Z * Y^T (Y sym)
        Ah = g_Zh[flag][bz] + (long)i0 * C_; Am = g_Zm[flag][bz] + (long)i0 * C_;
        Bh = g_Yh[flag][bz] + (long)j0 * C_; Bm = g_Ym[flag][bz] + (long)j0 * C_;
        sA = sB = C_; K = C_;
    } else if (mode == MODE_YZ) {
        int m = bz & 7;
        sA = sB = C_; K = C_;
        if (bz < 8) {                          // Ynew = Y * G   (G sym)
            Ah = g_Yh[flag][m] + (long)i0 * C_; Am = g_Ym[flag][m] + (long)i0 * C_;
            Bh = g_Gh[m] + (long)j0 * C_;       Bm = g_Gm[m] + (long)j0 * C_;
        } else {                               // Znew = G * Z   (Z sym)
            Ah = g_Gh[m] + (long)i0 * C_;       Am = g_Gm[m] + (long)i0 * C_;
            Bh = g_Zh[flag][m] + (long)j0 * C_; Bm = g_Zm[flag][m] + (long)j0 * C_;
        }
    } else if (mode == MODE_COMBINE) {         // M = alpha * Y_style * Z_content^T
        Ah = g_Yh[0][4 + bz] + (long)i0 * C_; Am = g_Ym[0][4 + bz] + (long)i0 * C_;
        Bh = g_Zh[0][bz] + (long)j0 * C_;     Bm = g_Zm[0][bz] + (long)j0 * C_;
        sA = sB = C_; K = C_;
    } else {                                   // APPLY: out = M * Xc^T (+ s_mean)
        Ah = g_Mh[bz] + (long)i0 * C_;       Am = g_Mm[bz] + (long)i0 * C_;
        Bh = &g_th[bz][j0][0];               Bm = &g_tm[bz][j0][0];
        sA = sB = C_; K = C_;
    }

    extern __shared__ char dsm[];
    uint32_t sb = smem_u32(dsm);
    int tid = threadIdx.x, wid = tid >> 5, l = tid & 31;
    int wr = wid & 3, wc = wid >> 2;            // warp grid 4 (m) x 2 (n)

    // lane-invariant ldmatrix offsets (bytes, kk=0)
    uint32_t aoff[2], boff[4];
#pragma unroll
    for (int t = 0; t < 2; t++)
        aoff[t] = (uint32_t)(((wr * 32 + t * 16 + (l & 15)) * 40 + ((l >> 4) << 3)) * 2);
#pragma unroll
    for (int jp = 0; jp < 4; jp++) {
        int g = l >> 3;
        int row = wc * 64 + jp * 16 + (l & 7) + ((g >= 2) ? 8 : 0);
        boff[jp] = (uint32_t)((row * 40 + ((g & 1) << 3)) * 2);
    }

    float acc[2][8][4];
#pragma unroll
    for (int t = 0; t < 2; t++)
#pragma unroll
        for (int j = 0; j < 8; j++)
#pragma unroll
            for (int q = 0; q < 4; q++) acc[t][j][q] = 0.f;

    int nch = K / 32;
    fill_stage(sb, Ah, Am, Bh, Bm, sA, sB, tid); CP_COMMIT();
    fill_stage(sb + STAGE_BYTES, Ah + 32, Am + 32, Bh + 32, Bm + 32, sA, sB, tid); CP_COMMIT();

    for (int c = 0; c < nch; c++) {
        if (c + 1 < nch) CP_WAIT1(); else CP_WAIT0();
        __syncthreads();
        uint32_t stb = sb + (uint32_t)(c & 1) * STAGE_BYTES;
#pragma unroll
        for (int kk = 0; kk < 2; kk++) {
            uint32_t kof = (uint32_t)kk * 32;
            uint32_t fa[2][4], fm[2][4];
            ldsm4(fa[0], stb + aoff[0] + kof);
            ldsm4(fa[1], stb + aoff[1] + kof);
            ldsm4(fm[0], stb + TEN_BYTES + aoff[0] + kof);
            ldsm4(fm[1], stb + TEN_BYTES + aoff[1] + kof);
#pragma unroll
            for (int jp = 0; jp < 4; jp++) {
                uint32_t bh[4], bm2[4];
                ldsm4(bh,  stb + 2 * TEN_BYTES + boff[jp] + kof);
                ldsm4(bm2, stb + 3 * TEN_BYTES + boff[jp] + kof);
#pragma unroll
                for (int t = 0; t < 2; t++) {
                    mma16816(acc[t][2 * jp],     fa[t], &bh[0]);
                    mma16816(acc[t][2 * jp],     fa[t], &bm2[0]);
                    mma16816(acc[t][2 * jp],     fm[t], &bh[0]);
                    mma16816(acc[t][2 * jp + 1], fa[t], &bh[2]);
                    mma16816(acc[t][2 * jp + 1], fa[t], &bm2[2]);
                    mma16816(acc[t][2 * jp + 1], fm[t], &bh[2]);
                }
            }
        }
        __syncthreads();
        if (c + 2 < nch) {
            long ko = (long)(c + 2) * 32;
            fill_stage(sb + (uint32_t)(c & 1) * STAGE_BYTES,
                       Ah + ko, Am + ko, Bh + ko, Bm + ko, sA, sB, tid);
            CP_COMMIT();
        }
    }

    // ---------------- epilogue straight from registers ----------------
    int r0 = l >> 2, cp2 = (l & 3) * 2;
    float alpha = (mode == MODE_COMBINE) ? sqrtf(g_s[4 + bz] / g_s[bz]) : 1.0f;
    const float inv = 1.0f / (float)(N_ - 1);

#pragma unroll
    for (int t = 0; t < 2; t++) {
        int gia = i0 + wr * 32 + t * 16 + r0;     // rows gia, gia+8
#pragma unroll
        for (int j = 0; j < 8; j++) {
            int gj = j0 + wc * 64 + j * 8 + cp2;  // cols gj, gj+1
            float v00 = acc[t][j][0], v01 = acc[t][j][1];
            float v10 = acc[t][j][2], v11 = acc[t][j][3];

            if (mode == MODE_COV) {
                float* dst = &g_cov[bz][0];
                v00 *= inv; v01 *= inv; v10 *= inv; v11 *= inv;
                if (gj     == gia)     v00 += EPS_;
                if (gj + 1 == gia)     v01 += EPS_;
                if (gj     == gia + 8) v10 += EPS_;
                if (gj + 1 == gia + 8) v11 += EPS_;
                *(float2*)&dst[(long)gia * C_ + gj]       = make_float2(v00, v01);
                *(float2*)&dst[(long)(gia + 8) * C_ + gj] = make_float2(v10, v11);
                if (bx != by) {
                    dst[(long)gj * C_ + gia]           = v00;
                    dst[(long)(gj + 1) * C_ + gia]     = v01;
                    dst[(long)gj * C_ + gia + 8]       = v10;
                    dst[(long)(gj + 1) * C_ + gia + 8] = v11;
                }
            } else if (mode == MODE_APPLY) {
                float sm0 = g_mean[1][bz][gia], sm1 = g_mean[1][bz][gia + 8];
                float* o0 = outp + ((long)bz * C_ + gia) * N_ + gj;
                *(float2*)o0 = make_float2(v00 + sm0, v01 + sm0);
                float* o1 = outp + ((long)bz * C_ + gia + 8) * N_ + gj;
                *(float2*)o1 = make_float2(v10 + sm1, v11 + sm1);
            } else {
                __nv_bfloat16 *dh, *dm;
                if (mode == MODE_G) {
                    dh = g_Gh[bz]; dm = g_Gm[bz];
                    v00 = -0.5f * v00 + ((gj     == gia)     ? 1.5f : 0.f);
                    v01 = -0.5f * v01 + ((gj + 1 == gia)     ? 1.5f : 0.f);
                    v10 = -0.5f * v10 + ((gj     == gia + 8) ? 1.5f : 0.f);
                    v11 = -0.5f * v11 + ((gj + 1 == gia + 8) ? 1.5f : 0.f);
                } else if (mode == MODE_YZ) {
                    int m = bz & 7;
                    if (bz < 8) { dh = g_Yh[flag ^ 1][m]; dm = g_Ym[flag ^ 1][m]; }
                    else        { dh = g_Zh[flag ^ 1][m]; dm = g_Zm[flag ^ 1][m]; }
                } else {
                    dh = g_Mh[bz]; dm = g_Mm[bz];
                    v00 *= alpha; v01 *= alpha; v10 *= alpha; v11 *= alpha;
                }
                __nv_bfloat16 h00, m00, h01, m01, h10, m10, h11, m11;
                split2(v00, h00, m00); split2(v01, h01, m01);
                split2(v10, h10, m10); split2(v11, h11, m11);
                __nv_bfloat162 ph0; ph0.x = h00; ph0.y = h01;
                __nv_bfloat162 pm0; pm0.x = m00; pm0.y = m01;
                __nv_bfloat162 ph1; ph1.x = h10; ph1.y = h11;
                __nv_bfloat162 pm1; pm1.x = m10; pm1.y = m11;
                *(__nv_bfloat162*)&dh[(long)gia * C_ + gj]       = ph0;
                *(__nv_bfloat162*)&dm[(long)gia * C_ + gj]       = pm0;
                *(__nv_bfloat162*)&dh[(long)(gia + 8) * C_ + gj] = ph1;
                *(__nv_bfloat162*)&dm[(long)(gia + 8) * C_ + gj] = pm1;
                if (sym && bx != by) {
                    dh[(long)gj * C_ + gia] = h00;           dm[(long)gj * C_ + gia] = m00;
                    dh[(long)(gj + 1) * C_ + gia] = h01;     dm[(long)(gj + 1) * C_ + gia] = m01;
                    dh[(long)gj * C_ + gia + 8] = h10;       dm[(long)gj * C_ + gia + 8] = m10;
                    dh[(long)(gj + 1) * C_ + gia + 8] = h11; dm[(long)(gj + 1) * C_ + gia + 8] = m11;
                }
            }
        }
    }
}

// ---------------- launch sequence (graph-capturable, deterministic) ----------------
extern "C" void kernel_launch(void* const* d_in, const int* in_sizes, int n_in,
                              void* d_out, int out_size)
{
    const float* content = (const float*)d_in[0];
    const float* style   = (const float*)d_in[1];
    float* out = (float*)d_out;

    cudaFuncSetAttribute(mma_kernel, cudaFuncAttributeMaxDynamicSharedMemorySize, SMEM_DYN);

    means_kernel<<<4096, 256>>>(content, style);
    split_kernel<<<4096, 256>>>(content, style);
    transpose_kernel<<<dim3(N_ / 32, C_ / 32, B_), 256>>>(content);

    mma_kernel<<<dim3(4, 4, NMAT), 256, SMEM_DYN>>>(MODE_COV, 0, nullptr);
    scale_kernel<<<NMAT, 256>>>();
    init_ns_kernel<<<NMAT * C_ * C_ / 256, 256>>>();

    for (int it = 0; it < NS_ITERS; it++) {
        mma_kernel<<<dim3(4, 4, NMAT), 256, SMEM_DYN>>>(MODE_G, it & 1, nullptr);
        mma_kernel<<<dim3(4, 4, NMAT * 2), 256, SMEM_DYN>>>(MODE_YZ, it & 1, nullptr);
    }

    mma_kernel<<<dim3(4, 4, B_), 256, SMEM_DYN>>>(MODE_COMBINE, 0, nullptr);
    mma_kernel<<<dim3(N_ / 128, 4, B_), 256, SMEM_DYN>>>(MODE_APPLY, 0, out);
}

// round 8
// speedup vs baseline: 2.8055x; 1.1307x over previous
#include <cuda_runtime.h>
#include <cuda_bf16.h>
#include <math.h>
#include <stdint.h>

#define C_    512
#define N_    16384
#define B_    4
#define NMAT  8
#define EPS_  1e-5f
#define NS_ITERS 8
#define KSPLIT 4
#define KSEG  (N_ / KSPLIT)       // 4096

#define MODE_COV     0
#define MODE_G       1
#define MODE_YZ      2
#define MODE_COMBINE 3
#define MODE_APPLY   4

// SMEM: 4 tensors x 128 rows x 40(pad) bf16 = 10240B each; stage = 40960B; 3 stages
#define TEN_BYTES   10240
#define STAGE_BYTES 40960
#define SMEM_DYN    122880

// ---------------- device scratch (no allocations allowed) ----------------
__device__ float g_mean[2][B_][C_];                  // [0]=content, [1]=style
__device__ float g_cov[NMAT][C_ * C_];
__device__ float g_covp[KSPLIT][NMAT][C_ * C_];      // split-K raw partials
__device__ float g_s[NMAT], g_sinv[NMAT];
__device__ __nv_bfloat16 g_xh[2][B_][C_][N_];        // centered hi  [src][b][c][n]
__device__ __nv_bfloat16 g_xm[2][B_][C_][N_];        // centered mid
__device__ __nv_bfloat16 g_th[B_][N_][C_];           // content^T centered hi
__device__ __nv_bfloat16 g_tm[B_][N_][C_];           // content^T centered mid
__device__ __nv_bfloat16 g_Yh[2][NMAT][C_ * C_], g_Ym[2][NMAT][C_ * C_];
__device__ __nv_bfloat16 g_Zh[2][NMAT][C_ * C_], g_Zm[2][NMAT][C_ * C_];
__device__ __nv_bfloat16 g_Gh[NMAT][C_ * C_], g_Gm[NMAT][C_ * C_];
__device__ __nv_bfloat16 g_Mh[B_][C_ * C_], g_Mm[B_][C_ * C_];

// ---------------- PTX helpers (all sm_80+ features only) ----------------
__device__ __forceinline__ uint32_t smem_u32(const void* p) {
    uint32_t a;
    asm("{ .reg .u64 t; cvta.to.shared.u64 t, %1; cvt.u32.u64 %0, t; }" : "=r"(a) : "l"(p));
    return a;
}
#define CP_ASYNC(dst, src) asm volatile("cp.async.cg.shared.global [%0], [%1], 16;" :: "r"(dst), "l"(src))
#define CP_COMMIT()        asm volatile("cp.async.commit_group;" ::: "memory")
#define CP_WAIT2()         asm volatile("cp.async.wait_group 2;" ::: "memory")

__device__ __forceinline__ void ldsm4(uint32_t* r, uint32_t addr) {
    asm volatile("ldmatrix.sync.aligned.m8n8.x4.shared.b16 {%0,%1,%2,%3}, [%4];"
        : "=r"(r[0]), "=r"(r[1]), "=r"(r[2]), "=r"(r[3]) : "r"(addr));
}
__device__ __forceinline__ void mma16816(float* c, const uint32_t* a, const uint32_t* b) {
    asm volatile("mma.sync.aligned.m16n8k16.row.col.f32.bf16.bf16.f32 "
        "{%0,%1,%2,%3}, {%4,%5,%6,%7}, {%8,%9}, {%0,%1,%2,%3};"
        : "+f"(c[0]), "+f"(c[1]), "+f"(c[2]), "+f"(c[3])
        : "r"(a[0]), "r"(a[1]), "r"(a[2]), "r"(a[3]), "r"(b[0]), "r"(b[1]));
}
__device__ __forceinline__ void split2(float v, __nv_bfloat16& h, __nv_bfloat16& m) {
    h = __float2bfloat16(v);
    m = __float2bfloat16(v - __bfloat162float(h));
}

// ---------------- prep kernels ----------------
__global__ __launch_bounds__(256) void means_kernel(
    const float* __restrict__ content, const float* __restrict__ style)
{
    int idx = blockIdx.x;
    int src = idx >> 11, b = (idx >> 9) & 3, c = idx & 511;
    const float* X = (src ? style : content) + (size_t)(b * C_ + c) * N_;
    const float4* X4 = (const float4*)X;
    float sum = 0.f;
    for (int i = threadIdx.x; i < N_ / 4; i += 256) {
        float4 v = X4[i];
        sum += (v.x + v.y) + (v.z + v.w);
    }
    __shared__ float red[256];
    red[threadIdx.x] = sum;
    __syncthreads();
    for (int s = 128; s; s >>= 1) {
        if (threadIdx.x < s) red[threadIdx.x] += red[threadIdx.x + s];
        __syncthreads();
    }
    if (threadIdx.x == 0) g_mean[src][b][c] = red[0] * (1.0f / N_);
}

__global__ __launch_bounds__(256) void split_kernel(
    const float* __restrict__ content, const float* __restrict__ style)
{
    int idx = blockIdx.x;
    int src = idx >> 11, b = (idx >> 9) & 3, c = idx & 511;
    const float* X = (src ? style : content) + (size_t)(b * C_ + c) * N_;
    float mu = g_mean[src][b][c];
    __nv_bfloat162* H = (__nv_bfloat162*)&g_xh[src][b][c][0];
    __nv_bfloat162* M = (__nv_bfloat162*)&g_xm[src][b][c][0];
    for (int i = threadIdx.x; i < N_ / 4; i += 256) {
        float4 v = ((const float4*)X)[i];
        __nv_bfloat16 h0, m0, h1, m1, h2, m2, h3, m3;
        split2(v.x - mu, h0, m0); split2(v.y - mu, h1, m1);
        split2(v.z - mu, h2, m2); split2(v.w - mu, h3, m3);
        __nv_bfloat162 a, b2;
        a.x = h0; a.y = h1; b2.x = h2; b2.y = h3;
        H[2 * i] = a; H[2 * i + 1] = b2;
        a.x = m0; a.y = m1; b2.x = m2; b2.y = m3;
        M[2 * i] = a; M[2 * i + 1] = b2;
    }
}

__global__ __launch_bounds__(256) void transpose_kernel(const float* __restrict__ content)
{
    __shared__ float t[32][33];
    int b = blockIdx.z;
    int n0 = blockIdx.x * 32, c0 = blockIdx.y * 32;
    int tx = threadIdx.x & 31, ty = threadIdx.x >> 5;   // 32 x 8
    const float* X = content + (size_t)b * C_ * N_;
#pragma unroll
    for (int j = 0; j < 32; j += 8) {
        int c = c0 + ty + j;
        t[ty + j][tx] = X[(size_t)c * N_ + n0 + tx] - g_mean[0][b][c];
    }
    __syncthreads();
#pragma unroll
    for (int j = 0; j < 32; j += 8) {
        int n = n0 + ty + j, c = c0 + tx;
        __nv_bfloat16 h, m;
        split2(t[tx][ty + j], h, m);
        g_th[b][n][c] = h;
        g_tm[b][n][c] = m;
    }
}

// fold split-K partials: cov = sum(partials)*inv + eps*I
__global__ __launch_bounds__(256) void cov_reduce_kernel()
{
    int i = blockIdx.x * 256 + threadIdx.x;   // 8 * 262144
    int m = i >> 18;
    int r = i & (C_ * C_ - 1);
    float v = g_covp[0][m][r] + g_covp[1][m][r] + g_covp[2][m][r] + g_covp[3][m][r];
    v *= 1.0f / (float)(N_ - 1);
    if ((r >> 9) == (r & 511)) v += EPS_;
    g_cov[m][r] = v;
}

__global__ __launch_bounds__(256) void scale_kernel()
{
    int m = blockIdx.x;
    const float* covm = g_cov[m];
    float ss = 0.f;
    for (int i = threadIdx.x; i < C_ * C_; i += 256) {
        float v = covm[i];
        ss += v * v;
    }
    __shared__ float red[256];
    red[threadIdx.x] = ss;
    __syncthreads();
    for (int s = 128; s; s >>= 1) {
        if (threadIdx.x < s) red[threadIdx.x] += red[threadIdx.x + s];
        __syncthreads();
    }
    if (threadIdx.x == 0) {
        float sc = sqrtf(red[0]) * (1.0f / 2.5f);
        g_s[m] = sc;
        g_sinv[m] = 1.0f / sc;
    }
}

__global__ __launch_bounds__(256) void init_ns_kernel()
{
    int i = blockIdx.x * 256 + threadIdx.x;   // 8 * 262144
    int m = i >> 18;
    int r = i & (C_ * C_ - 1);
    float v = g_cov[m][r] * g_sinv[m];
    __nv_bfloat16 h, mm;
    split2(v, h, mm);
    g_Yh[0][m][r] = h;
    g_Ym[0][m][r] = mm;
    bool dg = ((r >> 9) == (r & 511));
    g_Zh[0][m][r] = __float2bfloat16(dg ? 1.0f : 0.0f);
    g_Zm[0][m][r] = __float2bfloat16(0.0f);
}

// ---------------- cp.async stage fill: 4 tensors x 128 rows x 32 bf16 ----------------
__device__ __forceinline__ void fill_stage(uint32_t sbase,
    const __nv_bfloat16* ah, const __nv_bfloat16* am,
    const __nv_bfloat16* bh, const __nv_bfloat16* bm,
    long sA, long sB, int tid)
{
#pragma unroll
    for (int t = tid; t < 512; t += 256) {
        int row = t >> 2, q = (t & 3) * 8;
        uint32_t d = sbase + (uint32_t)(row * 40 + q) * 2;
        long oa = (long)row * sA + q, ob = (long)row * sB + q;
        CP_ASYNC(d,                 ah + oa);
        CP_ASYNC(d + TEN_BYTES,     am + oa);
        CP_ASYNC(d + 2 * TEN_BYTES, bh + ob);
        CP_ASYNC(d + 3 * TEN_BYTES, bm + ob);
    }
}

// ---------------- warp-MMA tile GEMM: D(128x128) = A * B^T, bf16 hi/mid split ----------------
__global__ __launch_bounds__(256) void mma_kernel(int mode, int flag, float* __restrict__ outp)
{
    int bx = blockIdx.x, by = blockIdx.y, bz = blockIdx.z;
    bool sym = (mode <= MODE_YZ);
    if (sym && by > bx) return;               // upper-triangle tiles only; mirror in epilogue
    int i0 = by * 128, j0 = bx * 128;

    const __nv_bfloat16 *Ah, *Am, *Bh, *Bm;
    long sA, sB;
    int K;
    int mz = bz, sK = 0;
    if (mode == MODE_COV) {
        mz = bz & 7; sK = bz >> 3;            // mat, K-split
        int src = mz >> 2, b = mz & 3;
        long ks = (long)sK * KSEG;
        Ah = &g_xh[src][b][i0][0] + ks; Am = &g_xm[src][b][i0][0] + ks;
        Bh = &g_xh[src][b][j0][0] + ks; Bm = &g_xm[src][b][j0][0] + ks;
        sA = sB = N_; K = KSEG;
    } else if (mode == MODE_G) {              // G = (3I - Z*Y)/2 ; D = Z * Y^T (Y sym)
        Ah = g_Zh[flag][bz] + (long)i0 * C_; Am = g_Zm[flag][bz] + (long)i0 * C_;
        Bh = g_Yh[flag][bz] + (long)j0 * C_; Bm = g_Ym[flag][bz] + (long)j0 * C_;
        sA = sB = C_; K = C_;
    } else if (mode == MODE_YZ) {
        int m = bz & 7;
        sA = sB = C_; K = C_;
        if (bz < 8) {                          // Ynew = Y * G   (G sym)
            Ah = g_Yh[flag][m] + (long)i0 * C_; Am = g_Ym[flag][m] + (long)i0 * C_;
            Bh = g_Gh[m] + (long)j0 * C_;       Bm = g_Gm[m] + (long)j0 * C_;
        } else {                               // Znew = G * Z   (Z sym)
            Ah = g_Gh[m] + (long)i0 * C_;       Am = g_Gm[m] + (long)i0 * C_;
            Bh = g_Zh[flag][m] + (long)j0 * C_; Bm = g_Zm[flag][m] + (long)j0 * C_;
        }
    } else if (mode == MODE_COMBINE) {         // M = alpha * Y_style * Z_content^T
        Ah = g_Yh[0][4 + bz] + (long)i0 * C_; Am = g_Ym[0][4 + bz] + (long)i0 * C_;
        Bh = g_Zh[0][bz] + (long)j0 * C_;     Bm = g_Zm[0][bz] + (long)j0 * C_;
        sA = sB = C_; K = C_;
    } else {                                   // APPLY: out = M * Xc^T (+ s_mean)
        Ah = g_Mh[bz] + (long)i0 * C_;       Am = g_Mm[bz] + (long)i0 * C_;
        Bh = &g_th[bz][j0][0];               Bm = &g_tm[bz][j0][0];
        sA = sB = C_; K = C_;
    }

    extern __shared__ char dsm[];
    uint32_t sb = smem_u32(dsm);
    int tid = threadIdx.x, wid = tid >> 5, l = tid & 31;
    int wr = wid & 3, wc = wid >> 2;            // warp grid 4 (m) x 2 (n)

    // lane-invariant ldmatrix offsets (bytes, kk=0)
    uint32_t aoff[2], boff[4];
#pragma unroll
    for (int t = 0; t < 2; t++)
        aoff[t] = (uint32_t)(((wr * 32 + t * 16 + (l & 15)) * 40 + ((l >> 4) << 3)) * 2);
#pragma unroll
    for (int jp = 0; jp < 4; jp++) {
        int g = l >> 3;
        int row = wc * 64 + jp * 16 + (l & 7) + ((g >= 2) ? 8 : 0);
        boff[jp] = (uint32_t)((row * 40 + ((g & 1) << 3)) * 2);
    }

    float acc[2][8][4];
#pragma unroll
    for (int t = 0; t < 2; t++)
#pragma unroll
        for (int j = 0; j < 8; j++)
#pragma unroll
            for (int q = 0; q < 4; q++) acc[t][j][q] = 0.f;

    int nch = K / 32;
    // 3-stage prefill
#pragma unroll
    for (int s = 0; s < 3; s++) {
        long ko = (long)s * 32;
        fill_stage(sb + (uint32_t)s * STAGE_BYTES, Ah + ko, Am + ko, Bh + ko, Bm + ko, sA, sB, tid);
        CP_COMMIT();
    }

    int stg = 0;
    for (int c = 0; c < nch; c++) {
        CP_WAIT2();
        __syncthreads();
        uint32_t stb = sb + (uint32_t)stg * STAGE_BYTES;
#pragma unroll
        for (int kk = 0; kk < 2; kk++) {
            uint32_t kof = (uint32_t)kk * 32;
            uint32_t fa[2][4], fm[2][4];
            ldsm4(fa[0], stb + aoff[0] + kof);
            ldsm4(fa[1], stb + aoff[1] + kof);
            ldsm4(fm[0], stb + TEN_BYTES + aoff[0] + kof);
            ldsm4(fm[1], stb + TEN_BYTES + aoff[1] + kof);
#pragma unroll
            for (int jp = 0; jp < 4; jp++) {
                uint32_t bh[4], bm2[4];
                ldsm4(bh,  stb + 2 * TEN_BYTES + boff[jp] + kof);
                ldsm4(bm2, stb + 3 * TEN_BYTES + boff[jp] + kof);
                // pass-outer ordering: 4 independent accumulators between RAW reuses
                mma16816(acc[0][2 * jp],     fa[0], &bh[0]);
                mma16816(acc[0][2 * jp + 1], fa[0], &bh[2]);
                mma16816(acc[1][2 * jp],     fa[1], &bh[0]);
                mma16816(acc[1][2 * jp + 1], fa[1], &bh[2]);
                mma16816(acc[0][2 * jp],     fa[0], &bm2[0]);
                mma16816(acc[0][2 * jp + 1], fa[0], &bm2[2]);
                mma16816(acc[1][2 * jp],     fa[1], &bm2[0]);
                mma16816(acc[1][2 * jp + 1], fa[1], &bm2[2]);
                mma16816(acc[0][2 * jp],     fm[0], &bh[0]);
                mma16816(acc[0][2 * jp + 1], fm[0], &bh[2]);
                mma16816(acc[1][2 * jp],     fm[1], &bh[0]);
                mma16816(acc[1][2 * jp + 1], fm[1], &bh[2]);
            }
        }
        __syncthreads();
        if (c + 3 < nch) {
            long ko = (long)(c + 3) * 32;
            fill_stage(stb, Ah + ko, Am + ko, Bh + ko, Bm + ko, sA, sB, tid);
        }
        CP_COMMIT();                    // empty group near tail keeps wait_group invariant
        stg = (stg == 2) ? 0 : stg + 1;
    }

    // ---------------- epilogue straight from registers ----------------
    int r0 = l >> 2, cp2 = (l & 3) * 2;
    float alpha = (mode == MODE_COMBINE) ? sqrtf(g_s[4 + bz] / g_s[bz]) : 1.0f;

#pragma unroll
    for (int t = 0; t < 2; t++) {
        int gia = i0 + wr * 32 + t * 16 + r0;     // rows gia, gia+8
#pragma unroll
        for (int j = 0; j < 8; j++) {
            int gj = j0 + wc * 64 + j * 8 + cp2;  // cols gj, gj+1
            float v00 = acc[t][j][0], v01 = acc[t][j][1];
            float v10 = acc[t][j][2], v11 = acc[t][j][3];

            if (mode == MODE_COV) {
                float* dst = &g_covp[sK][mz][0];   // raw partial sums
                *(float2*)&dst[(long)gia * C_ + gj]       = make_float2(v00, v01);
                *(float2*)&dst[(long)(gia + 8) * C_ + gj] = make_float2(v10, v11);
                if (bx != by) {
                    dst[(long)gj * C_ + gia]           = v00;
                    dst[(long)(gj + 1) * C_ + gia]     = v01;
                    dst[(long)gj * C_ + gia + 8]       = v10;
                    dst[(long)(gj + 1) * C_ + gia + 8] = v11;
                }
            } else if (mode == MODE_APPLY) {
                float sm0 = g_mean[1][bz][gia], sm1 = g_mean[1][bz][gia + 8];
                float* o0 = outp + ((long)bz * C_ + gia) * N_ + gj;
                *(float2*)o0 = make_float2(v00 + sm0, v01 + sm0);
                float* o1 = outp + ((long)bz * C_ + gia + 8) * N_ + gj;
                *(float2*)o1 = make_float2(v10 + sm1, v11 + sm1);
            } else {
                __nv_bfloat16 *dh, *dm;
                if (mode == MODE_G) {
                    dh = g_Gh[bz]; dm = g_Gm[bz];
                    v00 = -0.5f * v00 + ((gj     == gia)     ? 1.5f : 0.f);
                    v01 = -0.5f * v01 + ((gj + 1 == gia)     ? 1.5f : 0.f);
                    v10 = -0.5f * v10 + ((gj     == gia + 8) ? 1.5f : 0.f);
                    v11 = -0.5f * v11 + ((gj + 1 == gia + 8) ? 1.5f : 0.f);
                } else if (mode == MODE_YZ) {
                    int m = bz & 7;
                    if (bz < 8) { dh = g_Yh[flag ^ 1][m]; dm = g_Ym[flag ^ 1][m]; }
                    else        { dh = g_Zh[flag ^ 1][m]; dm = g_Zm[flag ^ 1][m]; }
                } else {
                    dh = g_Mh[bz]; dm = g_Mm[bz];
                    v00 *= alpha; v01 *= alpha; v10 *= alpha; v11 *= alpha;
                }
                __nv_bfloat16 h00, m00, h01, m01, h10, m10, h11, m11;
                split2(v00, h00, m00); split2(v01, h01, m01);
                split2(v10, h10, m10); split2(v11, h11, m11);
                __nv_bfloat162 ph0; ph0.x = h00; ph0.y = h01;
                __nv_bfloat162 pm0; pm0.x = m00; pm0.y = m01;
                __nv_bfloat162 ph1; ph1.x = h10; ph1.y = h11;
                __nv_bfloat162 pm1; pm1.x = m10; pm1.y = m11;
                *(__nv_bfloat162*)&dh[(long)gia * C_ + gj]       = ph0;
                *(__nv_bfloat162*)&dm[(long)gia * C_ + gj]       = pm0;
                *(__nv_bfloat162*)&dh[(long)(gia + 8) * C_ + gj] = ph1;
                *(__nv_bfloat162*)&dm[(long)(gia + 8) * C_ + gj] = pm1;
                if (sym && bx != by) {
                    dh[(long)gj * C_ + gia] = h00;           dm[(long)gj * C_ + gia] = m00;
                    dh[(long)(gj + 1) * C_ + gia] = h01;     dm[(long)(gj + 1) * C_ + gia] = m01;
                    dh[(long)gj * C_ + gia + 8] = h10;       dm[(long)gj * C_ + gia + 8] = m10;
                    dh[(long)(gj + 1) * C_ + gia + 8] = h11; dm[(long)(gj + 1) * C_ + gia + 8] = m11;
                }
            }
        }
    }
}

// ---------------- launch sequence (graph-capturable, deterministic) ----------------
extern "C" void kernel_launch(void* const* d_in, const int* in_sizes, int n_in,
                              void* d_out, int out_size)
{
    const float* content = (const float*)d_in[0];
    const float* style   = (const float*)d_in[1];
    float* out = (float*)d_out;

    cudaFuncSetAttribute(mma_kernel, cudaFuncAttributeMaxDynamicSharedMemorySize, SMEM_DYN);

    means_kernel<<<4096, 256>>>(content, style);
    split_kernel<<<4096, 256>>>(content, style);
    transpose_kernel<<<dim3(N_ / 32, C_ / 32, B_), 256>>>(content);

    mma_kernel<<<dim3(4, 4, NMAT * KSPLIT), 256, SMEM_DYN>>>(MODE_COV, 0, nullptr);
    cov_reduce_kernel<<<NMAT * C_ * C_ / 256, 256>>>();
    scale_kernel<<<NMAT, 256>>>();
    init_ns_kernel<<<NMAT * C_ * C_ / 256, 256>>>();

    for (int it = 0; it < NS_ITERS; it++) {
        mma_kernel<<<dim3(4, 4, NMAT), 256, SMEM_DYN>>>(MODE_G, it & 1, nullptr);
        mma_kernel<<<dim3(4, 4, NMAT * 2), 256, SMEM_DYN>>>(MODE_YZ, it & 1, nullptr);
    }

    mma_kernel<<<dim3(4, 4, B_), 256, SMEM_DYN>>>(MODE_COMBINE, 0, nullptr);
    mma_kernel<<<dim3(N_ / 128, 4, B_), 256, SMEM_DYN>>>(MODE_APPLY, 0, out);
}

// round 9
// speedup vs baseline: 3.5049x; 1.2493x over previous
#include <cuda_runtime.h>
#include <cuda_bf16.h>
#include <math.h>
#include <stdint.h>

#define C_    512
#define N_    16384
#define B_    4
#define NMAT  8
#define EPS_  1e-5f
#define NS_ITERS 7
#define KSPLIT 8
#define KSEG  (N_ / KSPLIT)       // 2048

#define MODE_COV     0
#define MODE_G       1
#define MODE_YZ      2
#define MODE_COMBINE 3
#define MODE_APPLY   4

// SMEM: 4 tensors x 128 rows x 40(pad) bf16 = 10240B each; stage = 40960B; 2 stages
#define TEN_BYTES   10240
#define STAGE_BYTES 40960
#define SMEM_DYN    81920

// ---------------- device scratch (no allocations allowed) ----------------
__device__ float g_mean[2][B_][C_];                  // [0]=content, [1]=style
__device__ float g_cov[NMAT][C_ * C_];
__device__ float g_covp[KSPLIT][NMAT][C_ * C_];      // split-K raw partials
__device__ float g_s[NMAT], g_sinv[NMAT];
__device__ __nv_bfloat16 g_xh[2][B_][C_][N_];        // centered hi  [src][b][c][n]
__device__ __nv_bfloat16 g_xm[2][B_][C_][N_];        // centered mid
__device__ __nv_bfloat16 g_th[B_][N_][C_];           // content^T centered hi
__device__ __nv_bfloat16 g_tm[B_][N_][C_];           // content^T centered mid
__device__ __nv_bfloat16 g_Yh[2][NMAT][C_ * C_], g_Ym[2][NMAT][C_ * C_];
__device__ __nv_bfloat16 g_Zh[2][NMAT][C_ * C_], g_Zm[2][NMAT][C_ * C_];
__device__ __nv_bfloat16 g_Gh[NMAT][C_ * C_], g_Gm[NMAT][C_ * C_];
__device__ __nv_bfloat16 g_Mh[B_][C_ * C_], g_Mm[B_][C_ * C_];

// ---------------- PTX helpers (all sm_80+ features only) ----------------
__device__ __forceinline__ uint32_t smem_u32(const void* p) {
    uint32_t a;
    asm("{ .reg .u64 t; cvta.to.shared.u64 t, %1; cvt.u32.u64 %0, t; }" : "=r"(a) : "l"(p));
    return a;
}
#define CP_ASYNC(dst, src) asm volatile("cp.async.cg.shared.global [%0], [%1], 16;" :: "r"(dst), "l"(src))
#define CP_COMMIT()        asm volatile("cp.async.commit_group;" ::: "memory")
#define CP_WAIT1()         asm volatile("cp.async.wait_group 1;" ::: "memory")
#define CP_WAIT0()         asm volatile("cp.async.wait_group 0;" ::: "memory")

__device__ __forceinline__ void ldsm4(uint32_t* r, uint32_t addr) {
    asm volatile("ldmatrix.sync.aligned.m8n8.x4.shared.b16 {%0,%1,%2,%3}, [%4];"
        : "=r"(r[0]), "=r"(r[1]), "=r"(r[2]), "=r"(r[3]) : "r"(addr));
}
__device__ __forceinline__ void mma16816(float* c, const uint32_t* a, const uint32_t* b) {
    asm volatile("mma.sync.aligned.m16n8k16.row.col.f32.bf16.bf16.f32 "
        "{%0,%1,%2,%3}, {%4,%5,%6,%7}, {%8,%9}, {%0,%1,%2,%3};"
        : "+f"(c[0]), "+f"(c[1]), "+f"(c[2]), "+f"(c[3])
        : "r"(a[0]), "r"(a[1]), "r"(a[2]), "r"(a[3]), "r"(b[0]), "r"(b[1]));
}
__device__ __forceinline__ void split2(float v, __nv_bfloat16& h, __nv_bfloat16& m) {
    h = __float2bfloat16(v);
    m = __float2bfloat16(v - __bfloat162float(h));
}

// ---------------- fused means + center + split (single read of inputs) ----------------
__global__ __launch_bounds__(256) void means_split_kernel(
    const float* __restrict__ content, const float* __restrict__ style)
{
    int idx = blockIdx.x;
    int src = idx >> 11, b = (idx >> 9) & 3, c = idx & 511;
    const float4* X4 = (const float4*)((src ? style : content) + (size_t)(b * C_ + c) * N_);

    float4 v[16];
    float sum = 0.f;
#pragma unroll
    for (int j = 0; j < 16; j++) {
        v[j] = X4[threadIdx.x + j * 256];
        sum += (v[j].x + v[j].y) + (v[j].z + v[j].w);
    }
    __shared__ float red[256];
    red[threadIdx.x] = sum;
    __syncthreads();
    for (int s = 128; s; s >>= 1) {
        if (threadIdx.x < s) red[threadIdx.x] += red[threadIdx.x + s];
        __syncthreads();
    }
    float mu = red[0] * (1.0f / N_);
    if (threadIdx.x == 0) g_mean[src][b][c] = mu;

    __nv_bfloat162* H = (__nv_bfloat162*)&g_xh[src][b][c][0];
    __nv_bfloat162* M = (__nv_bfloat162*)&g_xm[src][b][c][0];
#pragma unroll
    for (int j = 0; j < 16; j++) {
        int i = threadIdx.x + j * 256;
        __nv_bfloat16 h0, m0, h1, m1, h2, m2, h3, m3;
        split2(v[j].x - mu, h0, m0); split2(v[j].y - mu, h1, m1);
        split2(v[j].z - mu, h2, m2); split2(v[j].w - mu, h3, m3);
        __nv_bfloat162 a, b2;
        a.x = h0; a.y = h1; b2.x = h2; b2.y = h3;
        H[2 * i] = a; H[2 * i + 1] = b2;
        a.x = m0; a.y = m1; b2.x = m2; b2.y = m3;
        M[2 * i] = a; M[2 * i + 1] = b2;
    }
}

__global__ __launch_bounds__(256) void transpose_kernel(const float* __restrict__ content)
{
    __shared__ float t[32][33];
    int b = blockIdx.z;
    int n0 = blockIdx.x * 32, c0 = blockIdx.y * 32;
    int tx = threadIdx.x & 31, ty = threadIdx.x >> 5;   // 32 x 8
    const float* X = content + (size_t)b * C_ * N_;
#pragma unroll
    for (int j = 0; j < 32; j += 8) {
        int c = c0 + ty + j;
        t[ty + j][tx] = X[(size_t)c * N_ + n0 + tx] - g_mean[0][b][c];
    }
    __syncthreads();
#pragma unroll
    for (int j = 0; j < 32; j += 8) {
        int n = n0 + ty + j, c = c0 + tx;
        __nv_bfloat16 h, m;
        split2(t[tx][ty + j], h, m);
        g_th[b][n][c] = h;
        g_tm[b][n][c] = m;
    }
}

// fold split-K partials: cov = sum(partials)*inv + eps*I
__global__ __launch_bounds__(256) void cov_reduce_kernel()
{
    int i = blockIdx.x * 256 + threadIdx.x;   // 8 * 262144
    int m = i >> 18;
    int r = i & (C_ * C_ - 1);
    float v = 0.f;
#pragma unroll
    for (int s = 0; s < KSPLIT; s++) v += g_covp[s][m][r];
    v *= 1.0f / (float)(N_ - 1);
    if ((r >> 9) == (r & 511)) v += EPS_;
    g_cov[m][r] = v;
}

__global__ __launch_bounds__(256) void scale_kernel()
{
    int m = blockIdx.x;
    const float* covm = g_cov[m];
    float ss = 0.f;
    for (int i = threadIdx.x; i < C_ * C_; i += 256) {
        float v = covm[i];
        ss += v * v;
    }
    __shared__ float red[256];
    red[threadIdx.x] = ss;
    __syncthreads();
    for (int s = 128; s; s >>= 1) {
        if (threadIdx.x < s) red[threadIdx.x] += red[threadIdx.x + s];
        __syncthreads();
    }
    if (threadIdx.x == 0) {
        float sc = sqrtf(red[0]) * (1.0f / 2.5f);
        g_s[m] = sc;
        g_sinv[m] = 1.0f / sc;
    }
}

__global__ __launch_bounds__(256) void init_ns_kernel()
{
    int i = blockIdx.x * 256 + threadIdx.x;   // 8 * 262144
    int m = i >> 18;
    int r = i & (C_ * C_ - 1);
    float v = g_cov[m][r] * g_sinv[m];
    __nv_bfloat16 h, mm;
    split2(v, h, mm);
    g_Yh[0][m][r] = h;
    g_Ym[0][m][r] = mm;
    bool dg = ((r >> 9) == (r & 511));
    g_Zh[0][m][r] = __float2bfloat16(dg ? 1.0f : 0.0f);
    g_Zm[0][m][r] = __float2bfloat16(0.0f);
}

// ---------------- cp.async stage fill: 4 tensors x 128 rows x 32 bf16 ----------------
__device__ __forceinline__ void fill_stage(uint32_t sbase,
    const __nv_bfloat16* ah, const __nv_bfloat16* am,
    const __nv_bfloat16* bh, const __nv_bfloat16* bm,
    long sA, long sB, int tid)
{
#pragma unroll
    for (int t = tid; t < 512; t += 256) {
        int row = t >> 2, q = (t & 3) * 8;
        uint32_t d = sbase + (uint32_t)(row * 40 + q) * 2;
        long oa = (long)row * sA + q, ob = (long)row * sB + q;
        CP_ASYNC(d,                 ah + oa);
        CP_ASYNC(d + TEN_BYTES,     am + oa);
        CP_ASYNC(d + 2 * TEN_BYTES, bh + ob);
        CP_ASYNC(d + 3 * TEN_BYTES, bm + ob);
    }
}

// ---------------- warp-MMA tile GEMM: D(128x128) = A * B^T, bf16 hi/mid split ----------------
__global__ __launch_bounds__(256, 2) void mma_kernel(int mode, int flag, float* __restrict__ outp)
{
    int bx = blockIdx.x, by = blockIdx.y, bz = blockIdx.z;
    bool sym = (mode <= MODE_YZ);
    if (sym && by > bx) return;               // upper-triangle tiles only; mirror in epilogue
    int i0 = by * 128, j0 = bx * 128;

    const __nv_bfloat16 *Ah, *Am, *Bh, *Bm;
    long sA, sB;
    int K;
    int mz = bz, sK = 0;
    if (mode == MODE_COV) {
        mz = bz & 7; sK = bz >> 3;            // mat, K-split
        int src = mz >> 2, b = mz & 3;
        long ks = (long)sK * KSEG;
        Ah = &g_xh[src][b][i0][0] + ks; Am = &g_xm[src][b][i0][0] + ks;
        Bh = &g_xh[src][b][j0][0] + ks; Bm = &g_xm[src][b][j0][0] + ks;
        sA = sB = N_; K = KSEG;
    } else if (mode == MODE_G) {              // G = (3I - Z*Y)/2 ; D = Z * Y^T (Y sym)
        Ah = g_Zh[flag][bz] + (long)i0 * C_; Am = g_Zm[flag][bz] + (long)i0 * C_;
        Bh = g_Yh[flag][bz] + (long)j0 * C_; Bm = g_Ym[flag][bz] + (long)j0 * C_;
        sA = sB = C_; K = C_;
    } else if (mode == MODE_YZ) {
        int m = bz & 7;
        sA = sB = C_; K = C_;
        if (bz < 8) {                          // Ynew = Y * G   (G sym)
            Ah = g_Yh[flag][m] + (long)i0 * C_; Am = g_Ym[flag][m] + (long)i0 * C_;
            Bh = g_Gh[m] + (long)j0 * C_;       Bm = g_Gm[m] + (long)j0 * C_;
        } else {                               // Znew = G * Z   (Z sym)
            Ah = g_Gh[m] + (long)i0 * C_;       Am = g_Gm[m] + (long)i0 * C_;
            Bh = g_Zh[flag][m] + (long)j0 * C_; Bm = g_Zm[flag][m] + (long)j0 * C_;
        }
    } else if (mode == MODE_COMBINE) {         // M = alpha * Y_style * Z_content^T
        Ah = g_Yh[0][4 + bz] + (long)i0 * C_; Am = g_Ym[0][4 + bz] + (long)i0 * C_;
        Bh = g_Zh[0][bz] + (long)j0 * C_;     Bm = g_Zm[0][bz] + (long)j0 * C_;
        sA = sB = C_; K = C_;
    } else {                                   // APPLY: out = M * Xc^T (+ s_mean)
        Ah = g_Mh[bz] + (long)i0 * C_;       Am = g_Mm[bz] + (long)i0 * C_;
        Bh = &g_th[bz][j0][0];               Bm = &g_tm[bz][j0][0];
        sA = sB = C_; K = C_;
    }

    extern __shared__ char dsm[];
    uint32_t sb = smem_u32(dsm);
    int tid = threadIdx.x, wid = tid >> 5, l = tid & 31;
    int wr = wid & 3, wc = wid >> 2;            // warp grid 4 (m) x 2 (n)

    // lane-invariant ldmatrix offsets (bytes, kk=0)
    uint32_t aoff[2], boff[4];
#pragma unroll
    for (int t = 0; t < 2; t++)
        aoff[t] = (uint32_t)(((wr * 32 + t * 16 + (l & 15)) * 40 + ((l >> 4) << 3)) * 2);
#pragma unroll
    for (int jp = 0; jp < 4; jp++) {
        int g = l >> 3;
        int row = wc * 64 + jp * 16 + (l & 7) + ((g >= 2) ? 8 : 0);
        boff[jp] = (uint32_t)((row * 40 + ((g & 1) << 3)) * 2);
    }

    float acc[2][8][4];
#pragma unroll
    for (int t = 0; t < 2; t++)
#pragma unroll
        for (int j = 0; j < 8; j++)
#pragma unroll
            for (int q = 0; q < 4; q++) acc[t][j][q] = 0.f;

    int nch = K / 32;
    fill_stage(sb, Ah, Am, Bh, Bm, sA, sB, tid); CP_COMMIT();
    fill_stage(sb + STAGE_BYTES, Ah + 32, Am + 32, Bh + 32, Bm + 32, sA, sB, tid); CP_COMMIT();

    for (int c = 0; c < nch; c++) {
        if (c + 1 < nch) CP_WAIT1(); else CP_WAIT0();
        __syncthreads();
        uint32_t stb = sb + (uint32_t)(c & 1) * STAGE_BYTES;
#pragma unroll
        for (int kk = 0; kk < 2; kk++) {
            uint32_t kof = (uint32_t)kk * 32;
            uint32_t fa[2][4], fm[2][4];
            ldsm4(fa[0], stb + aoff[0] + kof);
            ldsm4(fa[1], stb + aoff[1] + kof);
            ldsm4(fm[0], stb + TEN_BYTES + aoff[0] + kof);
            ldsm4(fm[1], stb + TEN_BYTES + aoff[1] + kof);
#pragma unroll
            for (int jp = 0; jp < 4; jp++) {
                uint32_t bh[4], bm2[4];
                ldsm4(bh,  stb + 2 * TEN_BYTES + boff[jp] + kof);
                ldsm4(bm2, stb + 3 * TEN_BYTES + boff[jp] + kof);
                // pass-outer ordering: 4 independent accumulators between RAW reuses
                mma16816(acc[0][2 * jp],     fa[0], &bh[0]);
                mma16816(acc[0][2 * jp + 1], fa[0], &bh[2]);
                mma16816(acc[1][2 * jp],     fa[1], &bh[0]);
                mma16816(acc[1][2 * jp + 1], fa[1], &bh[2]);
                mma16816(acc[0][2 * jp],     fa[0], &bm2[0]);
                mma16816(acc[0][2 * jp + 1], fa[0], &bm2[2]);
                mma16816(acc[1][2 * jp],     fa[1], &bm2[0]);
                mma16816(acc[1][2 * jp + 1], fa[1], &bm2[2]);
                mma16816(acc[0][2 * jp],     fm[0], &bh[0]);
                mma16816(acc[0][2 * jp + 1], fm[0], &bh[2]);
                mma16816(acc[1][2 * jp],     fm[1], &bh[0]);
                mma16816(acc[1][2 * jp + 1], fm[1], &bh[2]);
            }
        }
        __syncthreads();
        if (c + 2 < nch) {
            long ko = (long)(c + 2) * 32;
            fill_stage(sb + (uint32_t)(c & 1) * STAGE_BYTES,
                       Ah + ko, Am + ko, Bh + ko, Bm + ko, sA, sB, tid);
            CP_COMMIT();
        }
    }

    // ---------------- epilogue straight from registers ----------------
    int r0 = l >> 2, cp2 = (l & 3) * 2;
    float alpha = (mode == MODE_COMBINE) ? sqrtf(g_s[4 + bz] / g_s[bz]) : 1.0f;

#pragma unroll
    for (int t = 0; t < 2; t++) {
        int gia = i0 + wr * 32 + t * 16 + r0;     // rows gia, gia+8
#pragma unroll
        for (int j = 0; j < 8; j++) {
            int gj = j0 + wc * 64 + j * 8 + cp2;  // cols gj, gj+1
            float v00 = acc[t][j][0], v01 = acc[t][j][1];
            float v10 = acc[t][j][2], v11 = acc[t][j][3];

            if (mode == MODE_COV) {
                float* dst = &g_covp[sK][mz][0];   // raw partial sums
                *(float2*)&dst[(long)gia * C_ + gj]       = make_float2(v00, v01);
                *(float2*)&dst[(long)(gia + 8) * C_ + gj] = make_float2(v10, v11);
                if (bx != by) {
                    dst[(long)gj * C_ + gia]           = v00;
                    dst[(long)(gj + 1) * C_ + gia]     = v01;
                    dst[(long)gj * C_ + gia + 8]       = v10;
                    dst[(long)(gj + 1) * C_ + gia + 8] = v11;
                }
            } else if (mode == MODE_APPLY) {
                float sm0 = g_mean[1][bz][gia], sm1 = g_mean[1][bz][gia + 8];
                float* o0 = outp + ((long)bz * C_ + gia) * N_ + gj;
                *(float2*)o0 = make_float2(v00 + sm0, v01 + sm0);
                float* o1 = outp + ((long)bz * C_ + gia + 8) * N_ + gj;
                *(float2*)o1 = make_float2(v10 + sm1, v11 + sm1);
            } else {
                __nv_bfloat16 *dh, *dm;
                if (mode == MODE_G) {
                    dh = g_Gh[bz]; dm = g_Gm[bz];
                    v00 = -0.5f * v00 + ((gj     == gia)     ? 1.5f : 0.f);
                    v01 = -0.5f * v01 + ((gj + 1 == gia)     ? 1.5f : 0.f);
                    v10 = -0.5f * v10 + ((gj     == gia + 8) ? 1.5f : 0.f);
                    v11 = -0.5f * v11 + ((gj + 1 == gia + 8) ? 1.5f : 0.f);
                } else if (mode == MODE_YZ) {
                    int m = bz & 7;
                    if (bz < 8) { dh = g_Yh[flag ^ 1][m]; dm = g_Ym[flag ^ 1][m]; }
                    else        { dh = g_Zh[flag ^ 1][m]; dm = g_Zm[flag ^ 1][m]; }
                } else {
                    dh = g_Mh[bz]; dm = g_Mm[bz];
                    v00 *= alpha; v01 *= alpha; v10 *= alpha; v11 *= alpha;
                }
                __nv_bfloat16 h00, m00, h01, m01, h10, m10, h11, m11;
                split2(v00, h00, m00); split2(v01, h01, m01);
                split2(v10, h10, m10); split2(v11, h11, m11);
                __nv_bfloat162 ph0; ph0.x = h00; ph0.y = h01;
                __nv_bfloat162 pm0; pm0.x = m00; pm0.y = m01;
                __nv_bfloat162 ph1; ph1.x = h10; ph1.y = h11;
                __nv_bfloat162 pm1; pm1.x = m10; pm1.y = m11;
                *(__nv_bfloat162*)&dh[(long)gia * C_ + gj]       = ph0;
                *(__nv_bfloat162*)&dm[(long)gia * C_ + gj]       = pm0;
                *(__nv_bfloat162*)&dh[(long)(gia + 8) * C_ + gj] = ph1;
                *(__nv_bfloat162*)&dm[(long)(gia + 8) * C_ + gj] = pm1;
                if (sym && bx != by) {
                    dh[(long)gj * C_ + gia] = h00;           dm[(long)gj * C_ + gia] = m00;
                    dh[(long)(gj + 1) * C_ + gia] = h01;     dm[(long)(gj + 1) * C_ + gia] = m01;
                    dh[(long)gj * C_ + gia + 8] = h10;       dm[(long)gj * C_ + gia + 8] = m10;
                    dh[(long)(gj + 1) * C_ + gia + 8] = h11; dm[(long)(gj + 1) * C_ + gia + 8] = m11;
                }
            }
        }
    }
}

// ---------------- launch sequence (graph-capturable, deterministic) ----------------
extern "C" void kernel_launch(void* const* d_in, const int* in_sizes, int n_in,
                              void* d_out, int out_size)
{
    const float* content = (const float*)d_in[0];
    const float* style   = (const float*)d_in[1];
    float* out = (float*)d_out;

    cudaFuncSetAttribute(mma_kernel, cudaFuncAttributeMaxDynamicSharedMemorySize, SMEM_DYN);

    means_split_kernel<<<4096, 256>>>(content, style);
    transpose_kernel<<<dim3(N_ / 32, C_ / 32, B_), 256>>>(content);

    mma_kernel<<<dim3(4, 4, NMAT * KSPLIT), 256, SMEM_DYN>>>(MODE_COV, 0, nullptr);
    cov_reduce_kernel<<<NMAT * C_ * C_ / 256, 256>>>();
    scale_kernel<<<NMAT, 256>>>();
    init_ns_kernel<<<NMAT * C_ * C_ / 256, 256>>>();

    for (int it = 0; it < NS_ITERS; it++) {
        mma_kernel<<<dim3(4, 4, NMAT), 256, SMEM_DYN>>>(MODE_G, it & 1, nullptr);
        mma_kernel<<<dim3(4, 4, NMAT * 2), 256, SMEM_DYN>>>(MODE_YZ, it & 1, nullptr);
    }

    mma_kernel<<<dim3(4, 4, B_), 256, SMEM_DYN>>>(MODE_COMBINE, 0, nullptr);
    mma_kernel<<<dim3(N_ / 128, 4, B_), 256, SMEM_DYN>>>(MODE_APPLY, 0, out);
}